// round 9
// baseline (speedup 1.0000x reference)
#include <cuda_runtime.h>
#include <cuda_bf16.h>
#include <cstdint>

#define Bb 32
#define Ll 1024
#define LMD 1024
#define Dd 128
#define Rr 3
#define NLAYERS 2
#define Cc 8
#define Nn (Bb*Ll)          // 32768
#define Ee 524288
#define NRr (Nn*Rr)         // 98304

// ---------------- scratch (device globals; no allocations allowed) ----------
__device__ float g_lm[Nn*Dd];        // post-LN lm features
__device__ float g_x[Nn*Dd];         // layer buffers
__device__ float g_x2[Nn*Dd];
__device__ float g_agg[(size_t)Nn*Rr*Dd]; // [N][R*D] mean-aggregated
__device__ float g_Wt[LMD*Dd];       // lm_W transposed -> [K=1024][128]
__device__ float g_logits_scratch[Nn*Cc];
__device__ int   g_cnt[NRr];
__device__ int   g_cursor[NRr];
__device__ int   g_off[NRr+1];
__device__ int   g_srcs[Ee];
__device__ float g_loss[2];          // {sum_nll, n_valid}
__device__ int   g_is64;             // 1 if int inputs are int64, 0 if int32

// ---------------- packed f32x2 helpers (FFMA2 via PTX) ----------------
__device__ __forceinline__ unsigned long long pack2(float x, float y) {
    unsigned long long r;
    asm("mov.b64 %0, {%1, %2};" : "=l"(r) : "f"(x), "f"(y));
    return r;
}
__device__ __forceinline__ void unpack2(unsigned long long v, float& x, float& y) {
    asm("mov.b64 {%0, %1}, %2;" : "=f"(x), "=f"(y) : "l"(v));
}
__device__ __forceinline__ void ffma2(unsigned long long& d,
                                      unsigned long long a, unsigned long long b) {
    asm("fma.rn.f32x2 %0, %1, %2, %0;" : "+l"(d) : "l"(a), "l"(b));
}

// ---------------- int dtype probe ----------------
// If data is int64 (values < 2^31, nonneg), every odd 32-bit word is 0.
__global__ void probe_k(const int* __restrict__ p) {
    __shared__ int bad;
    if (threadIdx.x == 0) bad = 0;
    __syncthreads();
    for (int i = threadIdx.x; i < 1024; i += blockDim.x)
        if (p[2*i + 1] != 0) bad = 1;
    __syncthreads();
    if (threadIdx.x == 0) g_is64 = bad ? 0 : 1;
}

__device__ __forceinline__ int load_int(const void* p, long long idx) {
    if (g_is64) return (int)((const long long*)p)[idx];
    return ((const int*)p)[idx];
}

// ---------------- utility kernels ----------------
__global__ void zero_k() {
    int i = blockIdx.x*blockDim.x + threadIdx.x;
    int stride = gridDim.x*blockDim.x;
    for (; i < NRr; i += stride) { g_cnt[i] = 0; g_cursor[i] = 0; }
    if (blockIdx.x == 0 && threadIdx.x < 2) g_loss[threadIdx.x] = 0.f;
}

__global__ void transW_k(const float* __restrict__ W) {   // W [128][1024] -> Wt [1024][128]
    int i = blockIdx.x*blockDim.x + threadIdx.x;          // 131072 elems
    if (i >= LMD*Dd) return;
    int h = i >> 10, k = i & 1023;
    g_Wt[k*Dd + h] = W[i];
}

// ---------------- GEMM: C[M x 128] = relu(A1@B1 + A2@B2 + bias) --------------
// A row-major [M x K], B row-major [K x 128]. BM=BN=128, BK=16, 256 thr.
// 8x8 microtile computed as 8 rows x 4 packed f32x2 column-pairs (FFMA2).
__global__ __launch_bounds__(256, 2)
void gemm_k(const float* __restrict__ A1, int K1, const float* __restrict__ B1,
            const float* __restrict__ A2, int K2, const float* __restrict__ B2,
            const float* __restrict__ bias, float* __restrict__ C)
{
    __shared__ float As[16][132];   // [k][m], stride 132 keeps 16B alignment
    __shared__ float Bs[16][128];   // [k][n]

    const int tid = threadIdx.x;
    const int ty  = tid >> 4;       // 0..15 row group
    const int txx = tid & 15;       // 0..15 col group
    const int m0  = blockIdx.x * 128;

    const int lrow = tid >> 1;      // 0..127   (A tile load)
    const int lk   = (tid & 1) * 8; // 0 or 8

    unsigned long long acc2[8][4];
#pragma unroll
    for (int i = 0; i < 8; i++)
#pragma unroll
        for (int j = 0; j < 4; j++) acc2[i][j] = 0ULL;

#pragma unroll 1
    for (int part = 0; part < 2; part++) {
        const float* A  = part ? A2 : A1;
        const float* Bm = part ? B2 : B1;
        const int K     = part ? K2 : K1;
        if (K == 0 || A == nullptr) continue;

#pragma unroll 1
        for (int kt = 0; kt < K; kt += 16) {
            // load A tile: row m0+lrow, cols kt+lk..+7
            const float* ap = A + (size_t)(m0 + lrow) * K + kt + lk;
            float4 a0 = *(const float4*)(ap);
            float4 a1 = *(const float4*)(ap + 4);
            As[lk+0][lrow] = a0.x; As[lk+1][lrow] = a0.y;
            As[lk+2][lrow] = a0.z; As[lk+3][lrow] = a0.w;
            As[lk+4][lrow] = a1.x; As[lk+5][lrow] = a1.y;
            As[lk+6][lrow] = a1.z; As[lk+7][lrow] = a1.w;
            // load B tile: contiguous 16x128 block
            const float4* bp = (const float4*)(Bm + (size_t)kt * 128);
            float4* bs4 = (float4*)&Bs[0][0];
            bs4[tid]       = bp[tid];
            bs4[tid + 256] = bp[tid + 256];
            __syncthreads();

#pragma unroll
            for (int kk = 0; kk < 16; kk++) {
                float4 fa0 = *(const float4*)&As[kk][ty*8];
                float4 fa1 = *(const float4*)&As[kk][ty*8 + 4];
                float4 fb0 = *(const float4*)&Bs[kk][txx*8];
                float4 fb1 = *(const float4*)&Bs[kk][txx*8 + 4];
                unsigned long long b2[4];
                b2[0] = pack2(fb0.x, fb0.y);
                b2[1] = pack2(fb0.z, fb0.w);
                b2[2] = pack2(fb1.x, fb1.y);
                b2[3] = pack2(fb1.z, fb1.w);
                float a[8] = {fa0.x,fa0.y,fa0.z,fa0.w, fa1.x,fa1.y,fa1.z,fa1.w};
#pragma unroll
                for (int i = 0; i < 8; i++) {
                    unsigned long long a2 = pack2(a[i], a[i]);
#pragma unroll
                    for (int j = 0; j < 4; j++)
                        ffma2(acc2[i][j], a2, b2[j]);
                }
            }
            __syncthreads();
        }
    }

    // epilogue: +bias, relu, store
    float bcol[8];
#pragma unroll
    for (int j = 0; j < 8; j++) bcol[j] = bias[txx*8 + j];
#pragma unroll
    for (int i = 0; i < 8; i++) {
        int row = m0 + ty*8 + i;
        float* cp = C + (size_t)row * 128 + txx*8;
        float v[8];
#pragma unroll
        for (int j = 0; j < 4; j++) unpack2(acc2[i][j], v[2*j], v[2*j+1]);
#pragma unroll
        for (int j = 0; j < 8; j++) v[j] = fmaxf(v[j] + bcol[j], 0.f);
        *(float4*)(cp)     = make_float4(v[0], v[1], v[2], v[3]);
        *(float4*)(cp + 4) = make_float4(v[4], v[5], v[6], v[7]);
    }
}

// ---------------- LayerNorm over D=128, one warp per row ----------------
__global__ void ln_k(const float* __restrict__ in, const float* __restrict__ gam,
                     const float* __restrict__ bet, float* __restrict__ out)
{
    int wid = threadIdx.x >> 5, lane = threadIdx.x & 31;
    int row = blockIdx.x * 8 + wid;
    const float4* ip = (const float4*)(in + (size_t)row * 128);
    float4 v = ip[lane];
    float s  = v.x + v.y + v.z + v.w;
    float sq = v.x*v.x + v.y*v.y + v.z*v.z + v.w*v.w;
#pragma unroll
    for (int o = 16; o; o >>= 1) {
        s  += __shfl_xor_sync(0xffffffffu, s,  o);
        sq += __shfl_xor_sync(0xffffffffu, sq, o);
    }
    float mu  = s * (1.f/128.f);
    float var = sq * (1.f/128.f) - mu*mu;
    float inv = rsqrtf(var + 1e-5f);
    float4 gg = ((const float4*)gam)[lane];
    float4 bb = ((const float4*)bet)[lane];
    float4 o4;
    o4.x = (v.x - mu)*inv*gg.x + bb.x;
    o4.y = (v.y - mu)*inv*gg.y + bb.y;
    o4.z = (v.z - mu)*inv*gg.z + bb.z;
    o4.w = (v.w - mu)*inv*gg.w + bb.w;
    ((float4*)(out + (size_t)row * 128))[lane] = o4;
}

// ---------------- edge preprocessing ----------------
__global__ void hist_k(const void* __restrict__ ei, const void* __restrict__ et) {
    int i = blockIdx.x*blockDim.x + threadIdx.x;
    int stride = gridDim.x*blockDim.x;
    for (; i < Ee; i += stride) {
        int dst = load_int(ei, (long long)Ee + i);
        int rel = load_int(et, i);
        atomicAdd(&g_cnt[dst * Rr + rel], 1);
    }
}

__global__ void scan_k() {   // single block, 1024 threads; exclusive scan of g_cnt -> g_off
    __shared__ int wsum[32];
    __shared__ int s_carry;
    int tid = threadIdx.x, lane = tid & 31, wid = tid >> 5;
    if (tid == 0) s_carry = 0;
    __syncthreads();
    for (int base = 0; base < NRr; base += 1024) {
        int v = g_cnt[base + tid];
        int x = v;
#pragma unroll
        for (int o = 1; o < 32; o <<= 1) {
            int t = __shfl_up_sync(0xffffffffu, x, o);
            if (lane >= o) x += t;
        }
        if (lane == 31) wsum[wid] = x;
        __syncthreads();
        if (wid == 0) {
            int w = wsum[lane];
#pragma unroll
            for (int o = 1; o < 32; o <<= 1) {
                int t = __shfl_up_sync(0xffffffffu, w, o);
                if (lane >= o) w += t;
            }
            wsum[lane] = w;
        }
        __syncthreads();
        int incl = x + (wid ? wsum[wid-1] : 0);
        g_off[base + tid] = s_carry + incl - v;
        __syncthreads();
        if (tid == 1023) s_carry += incl;
        __syncthreads();
    }
    if (tid == 0) g_off[NRr] = s_carry;
}

__global__ void scatter_k(const void* __restrict__ ei, const void* __restrict__ et) {
    int i = blockIdx.x*blockDim.x + threadIdx.x;
    int stride = gridDim.x*blockDim.x;
    for (; i < Ee; i += stride) {
        int dst = load_int(ei, (long long)Ee + i);
        int rel = load_int(et, i);
        int src = load_int(ei, i);
        int seg = dst * Rr + rel;
        int pos = g_off[seg] + atomicAdd(&g_cursor[seg], 1);
        g_srcs[pos] = src;
    }
}

// ---------------- per-segment mean aggregation: warp/segment, no atomics -----
__global__ void agg_k(const float* __restrict__ x) {
    int warp = blockIdx.x * (blockDim.x >> 5) + (threadIdx.x >> 5);
    if (warp >= NRr) return;
    int lane = threadIdx.x & 31;
    int beg = g_off[warp], end = g_off[warp + 1];
    float a0 = 0.f, a1 = 0.f, a2 = 0.f, a3 = 0.f;
    for (int i = beg; i < end; i++) {
        const float* xr = x + (size_t)g_srcs[i] * 128;
        a0 += xr[lane];       a1 += xr[lane + 32];
        a2 += xr[lane + 64];  a3 += xr[lane + 96];
    }
    int c = end - beg;
    float inv = 1.f / (float)(c > 0 ? c : 1);
    int n = warp / Rr, r = warp % Rr;
    float* o = g_agg + (size_t)n * (Rr*Dd) + r * Dd;
    o[lane]      = a0 * inv;  o[lane + 32] = a1 * inv;
    o[lane + 64] = a2 * inv;  o[lane + 96] = a3 * inv;
}

// ---------------- classifier + masked CE; warp per row ----------------
__global__ void cls_k(const float* __restrict__ lm, const float* __restrict__ gx,
                      const float* __restrict__ W, const float* __restrict__ cb,
                      const void* __restrict__ labels, const void* __restrict__ amask,
                      float* __restrict__ logits_out)
{
    __shared__ float s_nll[8];
    __shared__ float s_val[8];
    int wid = threadIdx.x >> 5, lane = threadIdx.x & 31;
    int row = blockIdx.x * 8 + wid;

    // lane holds feat[lane*8 .. lane*8+7] of the 256-wide concat [lm | g]
    float4 f0, f1;
    if (lane < 16) {
        const float* p = lm + (size_t)row * 128 + lane * 8;
        f0 = *(const float4*)p; f1 = *(const float4*)(p + 4);
    } else {
        const float* p = gx + (size_t)row * 128 + (lane - 16) * 8;
        f0 = *(const float4*)p; f1 = *(const float4*)(p + 4);
    }
    float acc[8];
    const float4* W4 = (const float4*)W;   // [8][64 float4]
#pragma unroll
    for (int c = 0; c < 8; c++) {
        float4 w0 = W4[c*64 + lane*2];
        float4 w1 = W4[c*64 + lane*2 + 1];
        acc[c] = f0.x*w0.x + f0.y*w0.y + f0.z*w0.z + f0.w*w0.w
               + f1.x*w1.x + f1.y*w1.y + f1.z*w1.z + f1.w*w1.w;
    }
#pragma unroll
    for (int c = 0; c < 8; c++)
#pragma unroll
        for (int o = 16; o; o >>= 1)
            acc[c] += __shfl_xor_sync(0xffffffffu, acc[c], o);

    if (lane == 0) {
        float lg[8];
#pragma unroll
        for (int c = 0; c < 8; c++) lg[c] = acc[c] + cb[c];
        float mx = lg[0];
#pragma unroll
        for (int c = 1; c < 8; c++) mx = fmaxf(mx, lg[c]);
        float se = 0.f;
#pragma unroll
        for (int c = 0; c < 8; c++) se += expf(lg[c] - mx);
        float lse = mx + logf(se);
#pragma unroll
        for (int c = 0; c < 8; c++) logits_out[(size_t)row * 8 + c] = lg[c];
        int lab = load_int(labels, row);
        bool valid = (load_int(amask, row) == 1);
        s_nll[wid] = valid ? (lse - lg[lab]) : 0.f;
        s_val[wid] = valid ? 1.f : 0.f;
    }
    __syncthreads();
    if (threadIdx.x == 0) {
        float sn = 0.f, sv = 0.f;
#pragma unroll
        for (int i = 0; i < 8; i++) { sn += s_nll[i]; sv += s_val[i]; }
        atomicAdd(&g_loss[0], sn);
        atomicAdd(&g_loss[1], sv);
    }
}

__global__ void fin_k(float* __restrict__ out) {
    out[0] = g_loss[0] / fmaxf(g_loss[1], 1.f);
}

// ---------------- launch ----------------
extern "C" void kernel_launch(void* const* d_in, const int* in_sizes, int n_in,
                              void* d_out, int out_size)
{
    const float* outp   = (const float*)d_in[0];
    const void*  ei     = d_in[1];
    const void*  et     = d_in[2];
    const void*  amask  = d_in[3];
    const void*  labels = d_in[4];
    const float* lm_W   = (const float*)d_in[5];
    const float* lm_b   = (const float*)d_in[6];
    const float* ln_g   = (const float*)d_in[7];
    const float* ln_b   = (const float*)d_in[8];
    const float* W_rel  = (const float*)d_in[9];
    const float* W_root = (const float*)d_in[10];
    const float* conv_b = (const float*)d_in[11];
    const float* cls_W  = (const float*)d_in[12];
    const float* cls_b  = (const float*)d_in[13];
    float* out = (float*)d_out;

    void *p_lm, *p_x, *p_x2, *p_agg, *p_Wt, *p_lg;
    cudaGetSymbolAddress(&p_lm,  g_lm);
    cudaGetSymbolAddress(&p_x,   g_x);
    cudaGetSymbolAddress(&p_x2,  g_x2);
    cudaGetSymbolAddress(&p_agg, g_agg);
    cudaGetSymbolAddress(&p_Wt,  g_Wt);
    cudaGetSymbolAddress(&p_lg,  g_logits_scratch);
    float* lm  = (float*)p_lm;
    float* x1  = (float*)p_x;
    float* x2  = (float*)p_x2;
    float* agg = (float*)p_agg;
    float* Wt  = (float*)p_Wt;

    // dtype probe first: everything integer-typed depends on g_is64
    probe_k<<<1, 256>>>((const int*)ei);
    zero_k<<<96, 1024>>>();
    transW_k<<<512, 256>>>(lm_W);

    // LM head GEMM (relu + bias) -> x2 as pre-LN temp
    gemm_k<<<Nn/128, 256>>>(outp, LMD, Wt, nullptr, 0, nullptr, lm_b, x2);
    ln_k<<<Nn/8, 256>>>(x2, ln_g, ln_b, lm);

    // edge sort (counting sort by segment id)
    hist_k<<<512, 256>>>(ei, et);
    scan_k<<<1, 1024>>>();
    scatter_k<<<512, 256>>>(ei, et);

    // layer 0: aggregate from lm, GEMM(K=384 from agg + K=128 from lm)
    agg_k<<<NRr/8, 256>>>(lm);
    gemm_k<<<Nn/128, 256>>>(agg, Rr*Dd, W_rel,
                            lm, Dd, W_root,
                            conv_b, x1);
    // layer 1
    agg_k<<<NRr/8, 256>>>(x1);
    gemm_k<<<Nn/128, 256>>>(agg, Rr*Dd, W_rel + (size_t)Rr*Dd*Dd,
                            x1, Dd, W_root + (size_t)Dd*Dd,
                            conv_b + Dd, x2);

    // classifier + loss; respect whatever layout out_size implies
    const int LOGITS = Nn * Cc;
    if (out_size >= LOGITS + 1) {
        // loss scalar first, then logits
        cls_k<<<Nn/8, 256>>>(lm, x2, cls_W, cls_b, labels, amask, out + 1);
        fin_k<<<1, 1>>>(out);
    } else if (out_size >= LOGITS) {
        // logits only
        cls_k<<<Nn/8, 256>>>(lm, x2, cls_W, cls_b, labels, amask, out);
    } else {
        // loss only: logits go to device scratch
        cls_k<<<Nn/8, 256>>>(lm, x2, cls_W, cls_b, labels, amask, (float*)p_lg);
        fin_k<<<1, 1>>>(out);
    }
}

// round 10
// speedup vs baseline: 1.4707x; 1.4707x over previous
#include <cuda_runtime.h>
#include <cuda_bf16.h>
#include <cstdint>

#define Bb 32
#define Ll 1024
#define LMD 1024
#define Dd 128
#define Rr 3
#define NLAYERS 2
#define Cc 8
#define Nn (Bb*Ll)          // 32768
#define Ee 524288
#define NRr (Nn*Rr)         // 98304

typedef __nv_bfloat16 bf16;

// ---------------- scratch (device globals; no allocations allowed) ----------
__device__ float g_lm[Nn*Dd];         // post-LN lm features (f32, for cls + agg)
__device__ bf16  g_lmh[Nn*Dd], g_lml[Nn*Dd];
__device__ float g_x[Nn*Dd];          // layer-0 output f32 (for agg gather + split src)
__device__ bf16  g_xh[Nn*Dd], g_xl[Nn*Dd];
__device__ float g_x2[Nn*Dd];         // pre-LN temp / layer-1 output
__device__ bf16  g_aggh[(size_t)Nn*Rr*Dd], g_aggl[(size_t)Nn*Rr*Dd];
__device__ bf16  g_Ah[(size_t)Nn*LMD], g_Al[(size_t)Nn*LMD];   // split LM input
__device__ bf16  g_Wth[LMD*Dd], g_Wtl[LMD*Dd];                 // lm_W^T split
__device__ bf16  g_Wrelh[NLAYERS*Rr*Dd*Dd], g_Wrell[NLAYERS*Rr*Dd*Dd];
__device__ bf16  g_Wrooth[NLAYERS*Dd*Dd], g_Wrootl[NLAYERS*Dd*Dd];
__device__ float g_logits_scratch[Nn*Cc];
__device__ int   g_cnt[NRr];
__device__ int   g_cursor[NRr];
__device__ int   g_off[NRr+1];
__device__ int   g_srcs[Ee];
__device__ float g_loss[2];
__device__ int   g_is64;

// ---------------- small helpers ----------------
__device__ __forceinline__ uint32_t sptr(const void* p) {
    return (uint32_t)__cvta_generic_to_shared(p);
}
__device__ __forceinline__ void bfsplit(float v, bf16& h, bf16& l) {
    h = __float2bfloat16(v);
    l = __float2bfloat16(v - __bfloat162float(h));
}

// ldmatrix x4 (non-transposed) : A fragments
__device__ __forceinline__ void ldsm4(uint32_t& r0, uint32_t& r1, uint32_t& r2, uint32_t& r3,
                                      uint32_t addr) {
    asm volatile("ldmatrix.sync.aligned.m8n8.x4.shared.b16 {%0,%1,%2,%3}, [%4];"
                 : "=r"(r0), "=r"(r1), "=r"(r2), "=r"(r3) : "r"(addr));
}
// ldmatrix x4 transposed : B fragments from row-major [K][N]
__device__ __forceinline__ void ldsm4t(uint32_t& r0, uint32_t& r1, uint32_t& r2, uint32_t& r3,
                                       uint32_t addr) {
    asm volatile("ldmatrix.sync.aligned.m8n8.x4.trans.shared.b16 {%0,%1,%2,%3}, [%4];"
                 : "=r"(r0), "=r"(r1), "=r"(r2), "=r"(r3) : "r"(addr));
}
__device__ __forceinline__ void mma16816(float* c, const uint32_t* a, uint32_t b0, uint32_t b1) {
    asm volatile("mma.sync.aligned.m16n8k16.row.col.f32.bf16.bf16.f32 "
                 "{%0,%1,%2,%3},{%4,%5,%6,%7},{%8,%9},{%0,%1,%2,%3};"
                 : "+f"(c[0]), "+f"(c[1]), "+f"(c[2]), "+f"(c[3])
                 : "r"(a[0]), "r"(a[1]), "r"(a[2]), "r"(a[3]), "r"(b0), "r"(b1));
}

// ---------------- int dtype probe ----------------
__global__ void probe_k(const int* __restrict__ p) {
    __shared__ int bad;
    if (threadIdx.x == 0) bad = 0;
    __syncthreads();
    for (int i = threadIdx.x; i < 1024; i += blockDim.x)
        if (p[2*i + 1] != 0) bad = 1;
    __syncthreads();
    if (threadIdx.x == 0) g_is64 = bad ? 0 : 1;
}
__device__ __forceinline__ int load_int(const void* p, long long idx) {
    if (g_is64) return (int)((const long long*)p)[idx];
    return ((const int*)p)[idx];
}

// ---------------- utility kernels ----------------
__global__ void zero_k() {
    int i = blockIdx.x*blockDim.x + threadIdx.x;
    int stride = gridDim.x*blockDim.x;
    for (; i < NRr; i += stride) { g_cnt[i] = 0; g_cursor[i] = 0; }
    if (blockIdx.x == 0 && threadIdx.x < 2) g_loss[threadIdx.x] = 0.f;
}

// lm_W [128][1024] -> Wt [1024][128], split into bf16 hi/lo. Output-indexed.
__global__ void transWsplit_k(const float* __restrict__ W) {
    int o = blockIdx.x*blockDim.x + threadIdx.x;     // 131072
    if (o >= LMD*Dd) return;
    int k = o >> 7, h = o & 127;
    float v = W[h*LMD + k];
    bf16 hi, lo; bfsplit(v, hi, lo);
    g_Wth[o] = hi; g_Wtl[o] = lo;
}

// generic elementwise split
__global__ void splitW_k(const float* __restrict__ src, int n, bf16* __restrict__ h, bf16* __restrict__ l) {
    int i = blockIdx.x*blockDim.x + threadIdx.x;
    int stride = gridDim.x*blockDim.x;
    for (; i < n; i += stride) {
        bf16 hi, lo; bfsplit(src[i], hi, lo);
        h[i] = hi; l[i] = lo;
    }
}

// big split: LM input [N x 1024] f32 -> bf16 hi/lo, 4 floats per thread iter
__global__ void splitA_k(const float* __restrict__ src) {
    size_t i = (size_t)blockIdx.x*blockDim.x + threadIdx.x;
    size_t stride = (size_t)gridDim.x*blockDim.x;
    const size_t n4 = (size_t)Nn*LMD/4;
    for (size_t j = i; j < n4; j += stride) {
        float4 v = ((const float4*)src)[j];
        bf16 h0,h1,h2,h3,l0,l1,l2,l3;
        bfsplit(v.x,h0,l0); bfsplit(v.y,h1,l1); bfsplit(v.z,h2,l2); bfsplit(v.w,h3,l3);
        ((__nv_bfloat162*)g_Ah)[2*j]   = __halves2bfloat162(h0,h1);
        ((__nv_bfloat162*)g_Ah)[2*j+1] = __halves2bfloat162(h2,h3);
        ((__nv_bfloat162*)g_Al)[2*j]   = __halves2bfloat162(l0,l1);
        ((__nv_bfloat162*)g_Al)[2*j+1] = __halves2bfloat162(l2,l3);
    }
}

// ---------------- tensor-core GEMM with 3xBF16 split -------------------------
// C[M x 128] = relu( sum over parts of (Ah@Bh + Ah@Bl + Al@Bh) + bias )
// per part: pass (Ah, Bh+Bl dual) then (Al, Bh single).
// Block 128x128, BK=32, 256 threads = 8 warps (2 m x 4 n), warp tile 64x32.
__global__ __launch_bounds__(256, 2)
void gemm3_k(const bf16* __restrict__ A1h, const bf16* __restrict__ A1l, int K1,
             const bf16* __restrict__ B1h, const bf16* __restrict__ B1l,
             const bf16* __restrict__ A2h, const bf16* __restrict__ A2l, int K2,
             const bf16* __restrict__ B2h, const bf16* __restrict__ B2l,
             const float* __restrict__ bias, float* __restrict__ C,
             bf16* __restrict__ Ch, bf16* __restrict__ Cl)
{
    __shared__ bf16 As[128][40];        // pad 8 -> row stride 80B (16B-aligned, ldmatrix conflict-free)
    __shared__ bf16 Bsm[2][32][136];    // pad 8 -> row stride 272B

    const int tid  = threadIdx.x;
    const int wid  = tid >> 5;
    const int lane = tid & 31;
    const int wm   = wid >> 2;          // 0..1 -> m offset *64
    const int wn   = wid & 3;           // 0..3 -> n offset *32
    const int m0   = blockIdx.x * 128;
    const int g    = lane >> 2;         // row-in-frag
    const int q    = lane & 3;          // col-pair-in-frag

    float acc[4][4][4];
#pragma unroll
    for (int i = 0; i < 4; i++)
#pragma unroll
        for (int j = 0; j < 4; j++)
#pragma unroll
            for (int r = 0; r < 4; r++) acc[i][j][r] = 0.f;

    // 4 passes: (A1h,B1h+B1l), (A1l,B1h), (A2h,B2h+B2l), (A2l,B2h)
#pragma unroll 1
    for (int pass = 0; pass < 4; pass++) {
        const bf16* Ap; const bf16* Bp0; const bf16* Bp1; int K;
        if      (pass == 0) { Ap = A1h; Bp0 = B1h; Bp1 = B1l; K = K1; }
        else if (pass == 1) { Ap = A1l; Bp0 = B1h; Bp1 = nullptr; K = K1; }
        else if (pass == 2) { Ap = A2h; Bp0 = B2h; Bp1 = B2l; K = K2; }
        else                { Ap = A2l; Bp0 = B2h; Bp1 = nullptr; K = K2; }
        if (Ap == nullptr || K == 0) continue;
        const bool dual = (Bp1 != nullptr);

#pragma unroll 1
        for (int kt = 0; kt < K; kt += 32) {
            // ---- load A tile 128x32 (512 16B-chunks, 2 iters) ----
            {
                int c = tid;
#pragma unroll
                for (int it = 0; it < 2; it++, c += 256) {
                    int row = c >> 2, cc = c & 3;
                    uint4 v = *(const uint4*)(Ap + (size_t)(m0 + row) * K + kt + cc*8);
                    *(uint4*)&As[row][cc*8] = v;
                }
            }
            // ---- load B tiles 32x128 ----
            {
                int c = tid;
#pragma unroll
                for (int it = 0; it < 2; it++, c += 256) {
                    int row = c >> 4, cc = c & 15;
                    uint4 v = *(const uint4*)(Bp0 + (size_t)(kt + row) * 128 + cc*8);
                    *(uint4*)&Bsm[0][row][cc*8] = v;
                }
                if (dual) {
                    c = tid;
#pragma unroll
                    for (int it = 0; it < 2; it++, c += 256) {
                        int row = c >> 4, cc = c & 15;
                        uint4 v = *(const uint4*)(Bp1 + (size_t)(kt + row) * 128 + cc*8);
                        *(uint4*)&Bsm[1][row][cc*8] = v;
                    }
                }
            }
            __syncthreads();

#pragma unroll
            for (int ks = 0; ks < 32; ks += 16) {
                // A fragments: 4 m-frags of 16x16
                uint32_t af[4][4];
#pragma unroll
                for (int f = 0; f < 4; f++)
                    ldsm4(af[f][0], af[f][1], af[f][2], af[f][3],
                          sptr(&As[wm*64 + 16*f + (lane & 15)][ks + ((lane >> 4) << 3)]));
                // B hi fragments: 2 x4.trans loads cover 4 n-frags
                uint32_t bh[2][4];
#pragma unroll
                for (int t = 0; t < 2; t++)
                    ldsm4t(bh[t][0], bh[t][1], bh[t][2], bh[t][3],
                           sptr(&Bsm[0][ks + (lane & 15)][wn*32 + 16*t + ((lane >> 4) << 3)]));
#pragma unroll
                for (int mf = 0; mf < 4; mf++)
#pragma unroll
                    for (int nf = 0; nf < 4; nf++)
                        mma16816(acc[mf][nf], af[mf], bh[nf>>1][(nf&1)*2], bh[nf>>1][(nf&1)*2+1]);
                if (dual) {
                    uint32_t bl[2][4];
#pragma unroll
                    for (int t = 0; t < 2; t++)
                        ldsm4t(bl[t][0], bl[t][1], bl[t][2], bl[t][3],
                               sptr(&Bsm[1][ks + (lane & 15)][wn*32 + 16*t + ((lane >> 4) << 3)]));
#pragma unroll
                    for (int mf = 0; mf < 4; mf++)
#pragma unroll
                        for (int nf = 0; nf < 4; nf++)
                            mma16816(acc[mf][nf], af[mf], bl[nf>>1][(nf&1)*2], bl[nf>>1][(nf&1)*2+1]);
                }
            }
            __syncthreads();
        }
    }

    // ---- epilogue: +bias, relu, store f32 (+ optional bf16 split) ----
#pragma unroll
    for (int nf = 0; nf < 4; nf++) {
        int col = wn*32 + 8*nf + 2*q;
        float b0 = bias[col], b1 = bias[col + 1];
#pragma unroll
        for (int mf = 0; mf < 4; mf++) {
            int row0 = m0 + wm*64 + 16*mf + g;
            float v0 = fmaxf(acc[mf][nf][0] + b0, 0.f);
            float v1 = fmaxf(acc[mf][nf][1] + b1, 0.f);
            float v2 = fmaxf(acc[mf][nf][2] + b0, 0.f);
            float v3 = fmaxf(acc[mf][nf][3] + b1, 0.f);
            *(float2*)&C[(size_t)row0 * 128 + col]       = make_float2(v0, v1);
            *(float2*)&C[(size_t)(row0 + 8) * 128 + col] = make_float2(v2, v3);
            if (Ch) {
                bf16 h0,h1,h2,h3,l0,l1,l2,l3;
                bfsplit(v0,h0,l0); bfsplit(v1,h1,l1); bfsplit(v2,h2,l2); bfsplit(v3,h3,l3);
                *(__nv_bfloat162*)&Ch[(size_t)row0*128 + col]     = __halves2bfloat162(h0,h1);
                *(__nv_bfloat162*)&Ch[(size_t)(row0+8)*128 + col] = __halves2bfloat162(h2,h3);
                *(__nv_bfloat162*)&Cl[(size_t)row0*128 + col]     = __halves2bfloat162(l0,l1);
                *(__nv_bfloat162*)&Cl[(size_t)(row0+8)*128 + col] = __halves2bfloat162(l2,l3);
            }
        }
    }
}

// ---------------- LayerNorm over D=128, one warp per row; emits f32 + bf16 split
__global__ void ln_k(const float* __restrict__ in, const float* __restrict__ gam,
                     const float* __restrict__ bet, float* __restrict__ out)
{
    int wid = threadIdx.x >> 5, lane = threadIdx.x & 31;
    int row = blockIdx.x * 8 + wid;
    const float4* ip = (const float4*)(in + (size_t)row * 128);
    float4 v = ip[lane];
    float s  = v.x + v.y + v.z + v.w;
    float sq = v.x*v.x + v.y*v.y + v.z*v.z + v.w*v.w;
#pragma unroll
    for (int o = 16; o; o >>= 1) {
        s  += __shfl_xor_sync(0xffffffffu, s,  o);
        sq += __shfl_xor_sync(0xffffffffu, sq, o);
    }
    float mu  = s * (1.f/128.f);
    float var = sq * (1.f/128.f) - mu*mu;
    float inv = rsqrtf(var + 1e-5f);
    float4 gg = ((const float4*)gam)[lane];
    float4 bb = ((const float4*)bet)[lane];
    float4 o4;
    o4.x = (v.x - mu)*inv*gg.x + bb.x;
    o4.y = (v.y - mu)*inv*gg.y + bb.y;
    o4.z = (v.z - mu)*inv*gg.z + bb.z;
    o4.w = (v.w - mu)*inv*gg.w + bb.w;
    ((float4*)(out + (size_t)row * 128))[lane] = o4;
    size_t base = (size_t)row * 128 + lane * 4;
    bf16 h0,h1,h2,h3,l0,l1,l2,l3;
    bfsplit(o4.x,h0,l0); bfsplit(o4.y,h1,l1); bfsplit(o4.z,h2,l2); bfsplit(o4.w,h3,l3);
    *(__nv_bfloat162*)&g_lmh[base]   = __halves2bfloat162(h0,h1);
    *(__nv_bfloat162*)&g_lmh[base+2] = __halves2bfloat162(h2,h3);
    *(__nv_bfloat162*)&g_lml[base]   = __halves2bfloat162(l0,l1);
    *(__nv_bfloat162*)&g_lml[base+2] = __halves2bfloat162(l2,l3);
}

// ---------------- edge preprocessing ----------------
__global__ void hist_k(const void* __restrict__ ei, const void* __restrict__ et) {
    int i = blockIdx.x*blockDim.x + threadIdx.x;
    int stride = gridDim.x*blockDim.x;
    for (; i < Ee; i += stride) {
        int dst = load_int(ei, (long long)Ee + i);
        int rel = load_int(et, i);
        atomicAdd(&g_cnt[dst * Rr + rel], 1);
    }
}

__global__ void scan_k() {
    __shared__ int wsum[32];
    __shared__ int s_carry;
    int tid = threadIdx.x, lane = tid & 31, wid = tid >> 5;
    if (tid == 0) s_carry = 0;
    __syncthreads();
    for (int base = 0; base < NRr; base += 1024) {
        int v = g_cnt[base + tid];
        int x = v;
#pragma unroll
        for (int o = 1; o < 32; o <<= 1) {
            int t = __shfl_up_sync(0xffffffffu, x, o);
            if (lane >= o) x += t;
        }
        if (lane == 31) wsum[wid] = x;
        __syncthreads();
        if (wid == 0) {
            int w = wsum[lane];
#pragma unroll
            for (int o = 1; o < 32; o <<= 1) {
                int t = __shfl_up_sync(0xffffffffu, w, o);
                if (lane >= o) w += t;
            }
            wsum[lane] = w;
        }
        __syncthreads();
        int incl = x + (wid ? wsum[wid-1] : 0);
        g_off[base + tid] = s_carry + incl - v;
        __syncthreads();
        if (tid == 1023) s_carry += incl;
        __syncthreads();
    }
    if (tid == 0) g_off[NRr] = s_carry;
}

__global__ void scatter_k(const void* __restrict__ ei, const void* __restrict__ et) {
    int i = blockIdx.x*blockDim.x + threadIdx.x;
    int stride = gridDim.x*blockDim.x;
    for (; i < Ee; i += stride) {
        int dst = load_int(ei, (long long)Ee + i);
        int rel = load_int(et, i);
        int src = load_int(ei, i);
        int seg = dst * Rr + rel;
        int pos = g_off[seg] + atomicAdd(&g_cursor[seg], 1);
        g_srcs[pos] = src;
    }
}

// ---------------- per-segment mean aggregation -> bf16 hi/lo, no atomics -----
__global__ void agg_k(const float* __restrict__ x) {
    int warp = blockIdx.x * (blockDim.x >> 5) + (threadIdx.x >> 5);
    if (warp >= NRr) return;
    int lane = threadIdx.x & 31;
    int beg = g_off[warp], end = g_off[warp + 1];
    float a0 = 0.f, a1 = 0.f, a2 = 0.f, a3 = 0.f;
    for (int i = beg; i < end; i++) {
        const float* xr = x + (size_t)g_srcs[i] * 128;
        a0 += xr[lane];       a1 += xr[lane + 32];
        a2 += xr[lane + 64];  a3 += xr[lane + 96];
    }
    int c = end - beg;
    float inv = 1.f / (float)(c > 0 ? c : 1);
    int n = warp / Rr, r = warp % Rr;
    size_t base = (size_t)n * (Rr*Dd) + r * Dd;
    float v; bf16 h, l;
    v = a0*inv; bfsplit(v,h,l); g_aggh[base+lane]    = h; g_aggl[base+lane]    = l;
    v = a1*inv; bfsplit(v,h,l); g_aggh[base+lane+32] = h; g_aggl[base+lane+32] = l;
    v = a2*inv; bfsplit(v,h,l); g_aggh[base+lane+64] = h; g_aggl[base+lane+64] = l;
    v = a3*inv; bfsplit(v,h,l); g_aggh[base+lane+96] = h; g_aggl[base+lane+96] = l;
}

// ---------------- classifier + masked CE; warp per row ----------------
__global__ void cls_k(const float* __restrict__ lm, const float* __restrict__ gx,
                      const float* __restrict__ W, const float* __restrict__ cb,
                      const void* __restrict__ labels, const void* __restrict__ amask,
                      float* __restrict__ logits_out)
{
    __shared__ float s_nll[8];
    __shared__ float s_val[8];
    int wid = threadIdx.x >> 5, lane = threadIdx.x & 31;
    int row = blockIdx.x * 8 + wid;

    float4 f0, f1;
    if (lane < 16) {
        const float* p = lm + (size_t)row * 128 + lane * 8;
        f0 = *(const float4*)p; f1 = *(const float4*)(p + 4);
    } else {
        const float* p = gx + (size_t)row * 128 + (lane - 16) * 8;
        f0 = *(const float4*)p; f1 = *(const float4*)(p + 4);
    }
    float acc[8];
    const float4* W4 = (const float4*)W;   // [8][64 float4]
#pragma unroll
    for (int c = 0; c < 8; c++) {
        float4 w0 = W4[c*64 + lane*2];
        float4 w1 = W4[c*64 + lane*2 + 1];
        acc[c] = f0.x*w0.x + f0.y*w0.y + f0.z*w0.z + f0.w*w0.w
               + f1.x*w1.x + f1.y*w1.y + f1.z*w1.z + f1.w*w1.w;
    }
#pragma unroll
    for (int c = 0; c < 8; c++)
#pragma unroll
        for (int o = 16; o; o >>= 1)
            acc[c] += __shfl_xor_sync(0xffffffffu, acc[c], o);

    if (lane == 0) {
        float lg[8];
#pragma unroll
        for (int c = 0; c < 8; c++) lg[c] = acc[c] + cb[c];
        float mx = lg[0];
#pragma unroll
        for (int c = 1; c < 8; c++) mx = fmaxf(mx, lg[c]);
        float se = 0.f;
#pragma unroll
        for (int c = 0; c < 8; c++) se += expf(lg[c] - mx);
        float lse = mx + logf(se);
#pragma unroll
        for (int c = 0; c < 8; c++) logits_out[(size_t)row * 8 + c] = lg[c];
        int lab = load_int(labels, row);
        bool valid = (load_int(amask, row) == 1);
        s_nll[wid] = valid ? (lse - lg[lab]) : 0.f;
        s_val[wid] = valid ? 1.f : 0.f;
    }
    __syncthreads();
    if (threadIdx.x == 0) {
        float sn = 0.f, sv = 0.f;
#pragma unroll
        for (int i = 0; i < 8; i++) { sn += s_nll[i]; sv += s_val[i]; }
        atomicAdd(&g_loss[0], sn);
        atomicAdd(&g_loss[1], sv);
    }
}

__global__ void fin_k(float* __restrict__ out) {
    out[0] = g_loss[0] / fmaxf(g_loss[1], 1.f);
}

// ---------------- launch ----------------
extern "C" void kernel_launch(void* const* d_in, const int* in_sizes, int n_in,
                              void* d_out, int out_size)
{
    const float* outp   = (const float*)d_in[0];
    const void*  ei     = d_in[1];
    const void*  et     = d_in[2];
    const void*  amask  = d_in[3];
    const void*  labels = d_in[4];
    const float* lm_W   = (const float*)d_in[5];
    const float* lm_b   = (const float*)d_in[6];
    const float* ln_g   = (const float*)d_in[7];
    const float* ln_b   = (const float*)d_in[8];
    const float* W_rel  = (const float*)d_in[9];
    const float* W_root = (const float*)d_in[10];
    const float* conv_b = (const float*)d_in[11];
    const float* cls_W  = (const float*)d_in[12];
    const float* cls_b  = (const float*)d_in[13];
    float* out = (float*)d_out;

    void *p_lm, *p_x, *p_x2, *p_lg;
    void *p_Ah, *p_Al, *p_Wth, *p_Wtl, *p_aggh, *p_aggl;
    void *p_lmh, *p_lml, *p_xh, *p_xl;
    void *p_Wrelh, *p_Wrell, *p_Wrooth, *p_Wrootl;
    cudaGetSymbolAddress(&p_lm,  g_lm);
    cudaGetSymbolAddress(&p_x,   g_x);
    cudaGetSymbolAddress(&p_x2,  g_x2);
    cudaGetSymbolAddress(&p_lg,  g_logits_scratch);
    cudaGetSymbolAddress(&p_Ah,  g_Ah);
    cudaGetSymbolAddress(&p_Al,  g_Al);
    cudaGetSymbolAddress(&p_Wth, g_Wth);
    cudaGetSymbolAddress(&p_Wtl, g_Wtl);
    cudaGetSymbolAddress(&p_aggh, g_aggh);
    cudaGetSymbolAddress(&p_aggl, g_aggl);
    cudaGetSymbolAddress(&p_lmh, g_lmh);
    cudaGetSymbolAddress(&p_lml, g_lml);
    cudaGetSymbolAddress(&p_xh,  g_xh);
    cudaGetSymbolAddress(&p_xl,  g_xl);
    cudaGetSymbolAddress(&p_Wrelh, g_Wrelh);
    cudaGetSymbolAddress(&p_Wrell, g_Wrell);
    cudaGetSymbolAddress(&p_Wrooth, g_Wrooth);
    cudaGetSymbolAddress(&p_Wrootl, g_Wrootl);

    float* lm  = (float*)p_lm;
    float* x1  = (float*)p_x;
    float* x2  = (float*)p_x2;
    bf16*  Ah  = (bf16*)p_Ah;   bf16* Al  = (bf16*)p_Al;
    bf16*  Wth = (bf16*)p_Wth;  bf16* Wtl = (bf16*)p_Wtl;
    bf16*  aggh = (bf16*)p_aggh; bf16* aggl = (bf16*)p_aggl;
    bf16*  lmh = (bf16*)p_lmh;  bf16* lml = (bf16*)p_lml;
    bf16*  xh  = (bf16*)p_xh;   bf16* xl  = (bf16*)p_xl;
    bf16*  Wrelh = (bf16*)p_Wrelh;   bf16* Wrell = (bf16*)p_Wrell;
    bf16*  Wrooth = (bf16*)p_Wrooth; bf16* Wrootl = (bf16*)p_Wrootl;

    // setup
    probe_k<<<1, 256>>>((const int*)ei);
    zero_k<<<96, 1024>>>();
    transWsplit_k<<<512, 256>>>(lm_W);
    splitW_k<<<96, 256>>>(W_rel,  NLAYERS*Rr*Dd*Dd, Wrelh,  Wrell);
    splitW_k<<<32, 256>>>(W_root, NLAYERS*Dd*Dd,    Wrooth, Wrootl);
    splitA_k<<<2048, 256>>>(outp);

    // LM head GEMM (bf16 3-split) -> x2 (pre-LN), then LN -> lm (+ lmh/lml)
    gemm3_k<<<Nn/128, 256>>>(Ah, Al, LMD, Wth, Wtl,
                             nullptr, nullptr, 0, nullptr, nullptr,
                             lm_b, x2, nullptr, nullptr);
    ln_k<<<Nn/8, 256>>>(x2, ln_g, ln_b, lm);

    // edge counting sort
    hist_k<<<512, 256>>>(ei, et);
    scan_k<<<1, 1024>>>();
    scatter_k<<<512, 256>>>(ei, et);

    // layer 0
    agg_k<<<NRr/8, 256>>>(lm);
    gemm3_k<<<Nn/128, 256>>>(aggh, aggl, Rr*Dd, Wrelh, Wrell,
                             lmh, lml, Dd, Wrooth, Wrootl,
                             conv_b, x1, xh, xl);
    // layer 1
    agg_k<<<NRr/8, 256>>>(x1);
    gemm3_k<<<Nn/128, 256>>>(aggh, aggl, Rr*Dd, Wrelh + Rr*Dd*Dd, Wrell + Rr*Dd*Dd,
                             xh, xl, Dd, Wrooth + Dd*Dd, Wrootl + Dd*Dd,
                             conv_b + Dd, x2, nullptr, nullptr);

    // classifier + loss
    const int LOGITS = Nn * Cc;
    if (out_size >= LOGITS + 1) {
        cls_k<<<Nn/8, 256>>>(lm, x2, cls_W, cls_b, labels, amask, out + 1);
        fin_k<<<1, 1>>>(out);
    } else if (out_size >= LOGITS) {
        cls_k<<<Nn/8, 256>>>(lm, x2, cls_W, cls_b, labels, amask, out);
    } else {
        cls_k<<<Nn/8, 256>>>(lm, x2, cls_W, cls_b, labels, amask, (float*)p_lg);
        fin_k<<<1, 1>>>(out);
    }
}